// round 15
// baseline (speedup 1.0000x reference)
#include <cuda_runtime.h>
#include <cuda_fp16.h>
#include <cstdint>

#define BB 4
#define SS 2048
#define HH 16
#define EE 1024

// ---------------- static scratch ----------------
__device__ __half g_x16[BB * SS * EE];
__device__ __half g_y16[BB * SS * EE];
__device__ __half g_wk16[EE * EE];
__device__ __half g_wv16[EE * EE];
__device__ __half g_wq16[EE * EE];
__device__ __half g_qh[BB * SS * EE];
__device__ __half g_kh[BB * SS * EE];
__device__ __half g_vth[BB * SS * EE];  // transposed [b*1024 + h*64 + dv][s]
__device__ __half g_aoh[BB * SS * EE];
__device__ __half g_wuh[64 * EE];

// ---------------- helpers ----------------
__device__ __forceinline__ uint32_t smem_u32(const void* p) {
    uint32_t a;
    asm("{ .reg .u64 t; cvta.to.shared.u64 t, %1; cvt.u32.u64 %0, t; }" : "=r"(a) : "l"(p));
    return a;
}
#define CPA(dst, src) asm volatile("cp.async.cg.shared.global [%0], [%1], 16;" ::"r"(dst), "l"(src))
#define CPC() asm volatile("cp.async.commit_group;" ::: "memory")
#define CPW(n) asm volatile("cp.async.wait_group %0;" ::"n"(n) : "memory")

__device__ __forceinline__ void ldsm4(uint32_t* r, uint32_t a) {
    asm volatile("ldmatrix.sync.aligned.m8n8.x4.shared.b16 {%0,%1,%2,%3}, [%4];"
                 : "=r"(r[0]), "=r"(r[1]), "=r"(r[2]), "=r"(r[3]) : "r"(a));
}
__device__ __forceinline__ void mma_f16(float* c, const uint32_t* a, const uint32_t* b) {
    asm volatile(
        "mma.sync.aligned.m16n8k16.row.col.f32.f16.f16.f32 "
        "{%0,%1,%2,%3}, {%4,%5,%6,%7}, {%8,%9}, {%0,%1,%2,%3};"
        : "+f"(c[0]), "+f"(c[1]), "+f"(c[2]), "+f"(c[3])
        : "r"(a[0]), "r"(a[1]), "r"(a[2]), "r"(a[3]), "r"(b[0]), "r"(b[1]));
}
__device__ __forceinline__ uint32_t ex2h2(uint32_t x) {
    uint32_t r;
    asm("ex2.approx.f16x2 %0, %1;" : "=r"(r) : "r"(x));
    return r;
}
__device__ __forceinline__ uint32_t packh2(float a, float b) {
    __half2 h = __floats2half2_rn(a, b);
    return *(uint32_t*)&h;
}

// ---------------------------------------------------------------------------
// fp32 -> fp16 planes; grid.y selects (x -> x16) or (y -> y16).
// ---------------------------------------------------------------------------
__global__ __launch_bounds__(256) void conv16x2(const float* __restrict__ x,
                                                const float* __restrict__ y,
                                                __half* __restrict__ dx,
                                                __half* __restrict__ dy) {
    const float* s = blockIdx.y ? y : x;
    __half* d = blockIdx.y ? dy : dx;
    int i = blockIdx.x * 256 + threadIdx.x;
    float4 v = ((const float4*)s)[i];
    __half2 h0 = __floats2half2_rn(v.x, v.y);
    __half2 h1 = __floats2half2_rn(v.z, v.w);
    ((__half2*)d)[2 * i] = h0;
    ((__half2*)d)[2 * i + 1] = h1;
}

// ---------------------------------------------------------------------------
// Transpose weights: z in {0,1,2}: W[1024][1024] -> T[n][1024].
// z==3: Wu[1024][64] -> Wut[64][1024] (only blockIdx.x < 2 active).
// ---------------------------------------------------------------------------
__global__ __launch_bounds__(256) void tsplit16x4(const float* __restrict__ Wk,
                                                  const float* __restrict__ Wv,
                                                  const float* __restrict__ Wq,
                                                  const float* __restrict__ Wu,
                                                  __half* __restrict__ Tk,
                                                  __half* __restrict__ Tv,
                                                  __half* __restrict__ Tq,
                                                  __half* __restrict__ Tu) {
    int z = blockIdx.z;
    if (z == 3 && blockIdx.x >= 2) return;
    const float* W = (z == 0) ? Wk : (z == 1) ? Wv : (z == 2) ? Wq : Wu;
    __half* T = (z == 0) ? Tk : (z == 1) ? Tv : (z == 2) ? Tq : Tu;
    int ncols = (z == 3) ? 64 : EE;
    __shared__ float t[32][33];
    int n0 = blockIdx.x * 32, k0 = blockIdx.y * 32;
    int tx = threadIdx.x & 31, ty = threadIdx.x >> 5;
#pragma unroll
    for (int i = 0; i < 32; i += 8)
        t[ty + i][tx] = W[(size_t)(k0 + ty + i) * ncols + n0 + tx];
    __syncthreads();
#pragma unroll
    for (int i = 0; i < 32; i += 8)
        T[(size_t)(n0 + ty + i) * EE + k0 + tx] = __float2half_rn(t[tx][ty + i]);
}

// ---------------------------------------------------------------------------
// Persistent merged projection GEMMs: 296 CTAs loop over 1536 logical tiles
// (z = 0:K, 1:V, 2:Q; 64 row-tiles x 8 col-tiles each).  3-stage single-
// barrier cp.async pipeline.  z==1 writes transposed (PV B-operand layout).
// ---------------------------------------------------------------------------
#define SSTR 72
#define PL16 (128 * SSTR)
#define STG16 (2 * PL16)
#define GSTAGES 3
#define GSM16 (GSTAGES * STG16 * 2)
#define NTILES (3 * 64 * 8)
#define GPERS 296

__global__ __launch_bounds__(256, 2) void gemm16x3(const __half* __restrict__ X,
                                                   const __half* __restrict__ Y,
                                                   const __half* __restrict__ Wk,
                                                   const __half* __restrict__ Wv,
                                                   const __half* __restrict__ Wq,
                                                   __half* __restrict__ Ck,
                                                   __half* __restrict__ Cv,
                                                   __half* __restrict__ Cq,
                                                   float sk, float sv, float sq) {
    extern __shared__ __half smh[];
    const uint32_t sb0 = smem_u32(smh);
    const int tid = threadIdx.x, lane = tid & 31, wid = tid >> 5;
    const int wm = wid >> 2, wn = wid & 3;

    const int aro = ((lane >> 3) & 1) * 8 + (lane & 7);
    const int ak = (lane >> 4) * 8;
    const int bro = (lane >> 4) * 8 + (lane & 7);
    const int bk = ((lane >> 3) & 1) * 8;

    for (int t = blockIdx.x; t < NTILES; t += GPERS) {
        const int z = t >> 9;          // t / 512
        const int r = t & 511;
        const int brow = (r >> 3) * 128;
        const int bcol = (r & 7) * 128;

        const __half* A = (z == 2) ? Y : X;
        const __half* B = (z == 0) ? Wk : (z == 1) ? Wv : Wq;
        __half* C = (z == 0) ? Ck : (z == 1) ? Cv : Cq;
        const float scale = (z == 0) ? sk : (z == 1) ? sv : sq;

        auto do_stage = [&](int s, int c) {
            uint32_t base = sb0 + s * STG16 * 2;
#pragma unroll
            for (int it = 0; it < 4; it++) {
                int ch = tid + it * 256;
                int row = ch >> 3, kk = (ch & 7) * 8;
                uint32_t so = (uint32_t)(row * SSTR + kk) * 2;
                CPA(base + so, A + (size_t)(brow + row) * EE + c * 64 + kk);
                CPA(base + PL16 * 2 + so, B + (size_t)(bcol + row) * EE + c * 64 + kk);
            }
        };

        float acc[4][4][4];
#pragma unroll
        for (int mi = 0; mi < 4; mi++)
#pragma unroll
            for (int nj = 0; nj < 4; nj++)
#pragma unroll
                for (int q = 0; q < 4; q++) acc[mi][nj][q] = 0.0f;

        // barrier: previous tile's compute fully drained before restaging
        __syncthreads();

        do_stage(0, 0);
        CPC();
        do_stage(1, 1);
        CPC();

        int sidx = 0;
        for (int c0 = 0; c0 < 16; c0++) {
            if (c0 < 15) { CPW(1); } else { CPW(0); }
            __syncthreads();
            if (c0 + 2 < 16) {
                int ns = sidx + 2;
                if (ns >= GSTAGES) ns -= GSTAGES;
                do_stage(ns, c0 + 2);
                CPC();
            }

            uint32_t uA = sb0 + sidx * STG16 * 2;
            uint32_t uB = uA + PL16 * 2;
#pragma unroll
            for (int ks = 0; ks < 4; ks++) {
                int k0 = ks * 16;
                uint32_t ah[4][4], bh[4][2];
#pragma unroll
                for (int mi = 0; mi < 4; mi++)
                    ldsm4(ah[mi],
                          uA + (uint32_t)((wm * 64 + mi * 16 + aro) * SSTR + k0 + ak) * 2);
#pragma unroll
                for (int njp = 0; njp < 2; njp++) {
                    uint32_t t4[4];
                    ldsm4(t4,
                          uB + (uint32_t)((wn * 32 + njp * 16 + bro) * SSTR + k0 + bk) * 2);
                    bh[2 * njp][0] = t4[0]; bh[2 * njp][1] = t4[1];
                    bh[2 * njp + 1][0] = t4[2]; bh[2 * njp + 1][1] = t4[3];
                }
#pragma unroll
                for (int mi = 0; mi < 4; mi++)
#pragma unroll
                    for (int nj = 0; nj < 4; nj++) mma_f16(acc[mi][nj], ah[mi], bh[nj]);
            }
            sidx = (sidx + 1 == GSTAGES) ? 0 : sidx + 1;
        }

#pragma unroll
        for (int mi = 0; mi < 4; mi++) {
#pragma unroll
            for (int nj = 0; nj < 4; nj++) {
                int row = brow + wm * 64 + mi * 16 + (lane >> 2);
                int col = bcol + wn * 32 + nj * 8 + (lane & 3) * 2;
                float v00 = acc[mi][nj][0] * scale, v01 = acc[mi][nj][1] * scale;
                float v10 = acc[mi][nj][2] * scale, v11 = acc[mi][nj][3] * scale;
                if (z != 1) {
                    uint32_t p0 = packh2(v00, v01), p1 = packh2(v10, v11);
                    *(uint32_t*)&C[(size_t)row * EE + col] = p0;
                    *(uint32_t*)&C[(size_t)(row + 8) * EE + col] = p1;
                } else {
                    float vs[4] = {v00, v01, v10, v11};
#pragma unroll
                    for (int e = 0; e < 4; e++) {
                        int rr = row + (e >> 1) * 8;
                        int cc = col + (e & 1);
                        C[(size_t)((rr >> 11) * 1024 + cc) * SS + (rr & 2047)] =
                            __float2half_rn(vs[e]);
                    }
                }
            }
        }
    }
}

// ---------------------------------------------------------------------------
// Fused attention (128 q-rows, 2 CTAs/SM), single barrier per kv-tile,
// log2-domain softmax, ex2.f16x2 fused with P repack, row-sums via ones-MMA.
// ---------------------------------------------------------------------------
#define ASTR 72
#define QPL (128 * ASTR)
#define KPL (64 * ASTR)
#define FSM ((QPL + 2 * 2 * KPL) * 2)

__global__ __launch_bounds__(256, 2) void flash_mma(const __half* __restrict__ Q,
                                                    const __half* __restrict__ K,
                                                    const __half* __restrict__ V,
                                                    __half* __restrict__ AOh) {
    extern __shared__ __half fsm[];
    const uint32_t sb = smem_u32(fsm);
    const int tid = threadIdx.x, lane = tid & 31, wid = tid >> 5;
    const int qt = blockIdx.x, h = blockIdx.y, b = blockIdx.z;
    const int q2 = (lane & 3) * 2;
    const int rq = wid * 16 + (lane >> 2);

    auto stageKV = [&](int s, int kt) {
        uint32_t base = sb + (QPL + s * 2 * KPL) * 2;
#pragma unroll
        for (int it = 0; it < 2; it++) {
            int ch = tid + it * 256;
            int row = ch >> 3, d8 = (ch & 7) * 8;
            uint32_t so = (uint32_t)(row * ASTR + d8) * 2;
            CPA(base + so, K + (size_t)(b * SS + kt * 64 + row) * EE + h * 64 + d8);
            CPA(base + KPL * 2 + so,
                V + (size_t)(b * 1024 + h * 64 + row) * SS + kt * 64 + d8);
        }
    };

#pragma unroll
    for (int it = 0; it < 4; it++) {
        int ch = tid + it * 256;
        int row = ch >> 3, d8 = (ch & 7) * 8;
        CPA(sb + (uint32_t)(row * ASTR + d8) * 2,
            Q + (size_t)(b * SS + qt * 128 + row) * EE + h * 64 + d8);
    }
    stageKV(0, 0);
    CPC();
    CPW(0);
    __syncthreads();

    const int aro = ((lane >> 3) & 1) * 8 + (lane & 7);
    const int ak = (lane >> 4) * 8;
    const int bro = (lane >> 4) * 8 + (lane & 7);
    const int bk = ((lane >> 3) & 1) * 8;

    uint32_t qf[4][4];
#pragma unroll
    for (int ks = 0; ks < 4; ks++)
        ldsm4(qf[ks], sb + (uint32_t)((wid * 16 + aro) * ASTR + ks * 16 + ak) * 2);

    const uint32_t ones[2] = {0x3C003C00u, 0x3C003C00u};
    float lacc[4] = {0.f, 0.f, 0.f, 0.f};
    float o[8][4];
#pragma unroll
    for (int nt = 0; nt < 8; nt++)
#pragma unroll
        for (int j = 0; j < 4; j++) o[nt][j] = 0.f;

    for (int kt = 0; kt < 32; kt++) {
        if (kt < 31) {
            stageKV((kt + 1) & 1, kt + 1);
            CPC();
        }

        uint32_t uK = sb + (QPL + (kt & 1) * 2 * KPL) * 2;
        uint32_t uV = uK + KPL * 2;

        float s[8][4];
#pragma unroll
        for (int nt = 0; nt < 8; nt++)
#pragma unroll
            for (int j = 0; j < 4; j++) s[nt][j] = 0.f;
#pragma unroll
        for (int ks = 0; ks < 4; ks++) {
            int k0 = ks * 16;
#pragma unroll
            for (int ntp = 0; ntp < 4; ntp++) {
                uint32_t t4[4];
                ldsm4(t4, uK + (uint32_t)((ntp * 16 + bro) * ASTR + k0 + bk) * 2);
                mma_f16(s[2 * ntp], qf[ks], t4);
                mma_f16(s[2 * ntp + 1], qf[ks], t4 + 2);
            }
        }

#pragma unroll
        for (int ks = 0; ks < 4; ks++) {
            int k0 = ks * 16;
            uint32_t a[4];
            a[0] = ex2h2(packh2(s[2 * ks][0], s[2 * ks][1]));
            a[1] = ex2h2(packh2(s[2 * ks][2], s[2 * ks][3]));
            a[2] = ex2h2(packh2(s[2 * ks + 1][0], s[2 * ks + 1][1]));
            a[3] = ex2h2(packh2(s[2 * ks + 1][2], s[2 * ks + 1][3]));
            mma_f16(lacc, a, ones);
#pragma unroll
            for (int ntp = 0; ntp < 4; ntp++) {
                uint32_t t4[4];
                ldsm4(t4, uV + (uint32_t)((ntp * 16 + bro) * ASTR + k0 + bk) * 2);
                mma_f16(o[2 * ntp], a, t4);
                mma_f16(o[2 * ntp + 1], a, t4 + 2);
            }
        }

        if (kt < 31) {
            CPW(0);
            __syncthreads();
        }
    }

    float inv0 = 1.0f / lacc[0], inv1 = 1.0f / lacc[2];
    size_t base = (size_t)(b * SS + qt * 128 + rq) * EE + h * 64;
#pragma unroll
    for (int nt = 0; nt < 8; nt++) {
        uint32_t hi0 = packh2(o[nt][0] * inv0, o[nt][1] * inv0);
        uint32_t hi1 = packh2(o[nt][2] * inv1, o[nt][3] * inv1);
        *(uint32_t*)&AOh[base + nt * 8 + q2] = hi0;
        *(uint32_t*)&AOh[base + (size_t)8 * EE + nt * 8 + q2] = hi1;
    }
}

// ---------------------------------------------------------------------------
// Output projection: C[M,64] = Ao[M,1024] @ Wut^T + bias, single-pass fp16.
// ---------------------------------------------------------------------------
#define PLA (128 * SSTR)
#define PLB (64 * SSTR)
#define OSM ((PLA + PLB) * 2)

__global__ __launch_bounds__(256) void out_mma(const __half* __restrict__ Aoh,
                                               const __half* __restrict__ Wh,
                                               const float* __restrict__ bias,
                                               float* __restrict__ C) {
    extern __shared__ __half osm[];
    const uint32_t sb = smem_u32(osm);
    const int tid = threadIdx.x, lane = tid & 31, wid = tid >> 5;
    const int brow = blockIdx.x * 128;

    const uint32_t uA = sb, uB = sb + PLA * 2;
    const int aro = ((lane >> 3) & 1) * 8 + (lane & 7);
    const int ak = (lane >> 4) * 8;
    const int bro = (lane >> 4) * 8 + (lane & 7);
    const int bk = ((lane >> 3) & 1) * 8;

    float acc[8][4];
#pragma unroll
    for (int nj = 0; nj < 8; nj++)
#pragma unroll
        for (int q = 0; q < 4; q++) acc[nj][q] = 0.0f;

    for (int c0 = 0; c0 < 16; c0++) {
#pragma unroll
        for (int it = 0; it < 4; it++) {
            int ch = tid + it * 256;
            int row = ch >> 3, kk = (ch & 7) * 8;
            *(uint4*)&osm[row * SSTR + kk] =
                *(const uint4*)(Aoh + (size_t)(brow + row) * EE + c0 * 64 + kk);
        }
#pragma unroll
        for (int it = 0; it < 2; it++) {
            int ch = tid + it * 256;
            int row = ch >> 3, kk = (ch & 7) * 8;
            *(uint4*)&osm[PLA + row * SSTR + kk] =
                *(const uint4*)(Wh + (size_t)row * EE + c0 * 64 + kk);
        }
        __syncthreads();

#pragma unroll
        for (int ks = 0; ks < 4; ks++) {
            int k0 = ks * 16;
            uint32_t ah[4], bh[8][2];
            ldsm4(ah, uA + (uint32_t)((wid * 16 + aro) * SSTR + k0 + ak) * 2);
#pragma unroll
            for (int njp = 0; njp < 4; njp++) {
                uint32_t t4[4];
                ldsm4(t4, uB + (uint32_t)((njp * 16 + bro) * SSTR + k0 + bk) * 2);
                bh[2 * njp][0] = t4[0]; bh[2 * njp][1] = t4[1];
                bh[2 * njp + 1][0] = t4[2]; bh[2 * njp + 1][1] = t4[3];
            }
#pragma unroll
            for (int nj = 0; nj < 8; nj++) mma_f16(acc[nj], ah, bh[nj]);
        }
        __syncthreads();
    }

    int row = brow + wid * 16 + (lane >> 2);
    int colb = (lane & 3) * 2;
#pragma unroll
    for (int nj = 0; nj < 8; nj++) {
        int col = nj * 8 + colb;
        float2 bv = *(const float2*)(bias + col);
        float2 w0 = {acc[nj][0] + bv.x, acc[nj][1] + bv.y};
        float2 w1 = {acc[nj][2] + bv.x, acc[nj][3] + bv.y};
        *(float2*)&C[(size_t)row * 64 + col] = w0;
        *(float2*)&C[(size_t)(row + 8) * 64 + col] = w1;
    }
}

// ---------------------------------------------------------------------------
extern "C" void kernel_launch(void* const* d_in, const int* in_sizes, int n_in,
                              void* d_out, int out_size) {
    const float* x = (const float*)d_in[0];
    const float* y = (const float*)d_in[1];
    const float* Wv = (const float*)d_in[2];
    const float* Wk = (const float*)d_in[3];
    const float* Wq = (const float*)d_in[4];
    const float* Wu = (const float*)d_in[5];
    const float* bu = (const float*)d_in[6];
    float* out = (float*)d_out;

    __half *x16, *y16, *wk16, *wv16, *wq16, *qh, *kh, *vth, *aoh, *wuh;
    cudaGetSymbolAddress((void**)&x16, g_x16);
    cudaGetSymbolAddress((void**)&y16, g_y16);
    cudaGetSymbolAddress((void**)&wk16, g_wk16);
    cudaGetSymbolAddress((void**)&wv16, g_wv16);
    cudaGetSymbolAddress((void**)&wq16, g_wq16);
    cudaGetSymbolAddress((void**)&qh, g_qh);
    cudaGetSymbolAddress((void**)&kh, g_kh);
    cudaGetSymbolAddress((void**)&vth, g_vth);
    cudaGetSymbolAddress((void**)&aoh, g_aoh);
    cudaGetSymbolAddress((void**)&wuh, g_wuh);

    const int M = BB * SS;  // 8192
    const float qk_scale = 0.17677669529663687f;           // 1024^-0.25
    const float q_scale = qk_scale * 1.4426950408889634f;  // fold log2(e) into Q

    dim3 gc(M * EE / 1024, 2);
    conv16x2<<<gc, 256>>>(x, y, x16, y16);
    dim3 gt(EE / 32, EE / 32, 4);
    tsplit16x4<<<gt, 256>>>(Wk, Wv, Wq, Wu, wk16, wv16, wq16, wuh);

    cudaFuncSetAttribute(gemm16x3, cudaFuncAttributeMaxDynamicSharedMemorySize, GSM16);
    gemm16x3<<<GPERS, 256, GSM16>>>(x16, y16, wk16, wv16, wq16, kh, vth, qh,
                                    qk_scale, 1.0f, q_scale);

    cudaFuncSetAttribute(flash_mma, cudaFuncAttributeMaxDynamicSharedMemorySize, FSM);
    dim3 ga(SS / 128, HH, BB);
    flash_mma<<<ga, 256, FSM>>>(qh, kh, vth, aoh);

    cudaFuncSetAttribute(out_mma, cudaFuncAttributeMaxDynamicSharedMemorySize, OSM);
    out_mma<<<M / 128, 256, OSM>>>(aoh, wuh, bu, out);
}

// round 16
// speedup vs baseline: 1.0048x; 1.0048x over previous
#include <cuda_runtime.h>
#include <cuda_fp16.h>
#include <cstdint>

#define BB 4
#define SS 2048
#define HH 16
#define EE 1024

// ---------------- static scratch ----------------
__device__ __half g_x16[BB * SS * EE];
__device__ __half g_y16[BB * SS * EE];
__device__ __half g_wk16[EE * EE];
__device__ __half g_wv16[EE * EE];
__device__ __half g_wq16[EE * EE];
__device__ __half g_qh[BB * SS * EE];
__device__ __half g_kh[BB * SS * EE];
__device__ __half g_vth[BB * SS * EE];  // transposed [b*1024 + h*64 + dv][s]
__device__ __half g_aoh[BB * SS * EE];
__device__ __half g_wuh[64 * EE];

// ---------------- helpers ----------------
__device__ __forceinline__ uint32_t smem_u32(const void* p) {
    uint32_t a;
    asm("{ .reg .u64 t; cvta.to.shared.u64 t, %1; cvt.u32.u64 %0, t; }" : "=r"(a) : "l"(p));
    return a;
}
#define CPA(dst, src) asm volatile("cp.async.cg.shared.global [%0], [%1], 16;" ::"r"(dst), "l"(src))
#define CPC() asm volatile("cp.async.commit_group;" ::: "memory")
#define CPW(n) asm volatile("cp.async.wait_group %0;" ::"n"(n) : "memory")

__device__ __forceinline__ void ldsm4(uint32_t* r, uint32_t a) {
    asm volatile("ldmatrix.sync.aligned.m8n8.x4.shared.b16 {%0,%1,%2,%3}, [%4];"
                 : "=r"(r[0]), "=r"(r[1]), "=r"(r[2]), "=r"(r[3]) : "r"(a));
}
__device__ __forceinline__ void mma_f16(float* c, const uint32_t* a, const uint32_t* b) {
    asm volatile(
        "mma.sync.aligned.m16n8k16.row.col.f32.f16.f16.f32 "
        "{%0,%1,%2,%3}, {%4,%5,%6,%7}, {%8,%9}, {%0,%1,%2,%3};"
        : "+f"(c[0]), "+f"(c[1]), "+f"(c[2]), "+f"(c[3])
        : "r"(a[0]), "r"(a[1]), "r"(a[2]), "r"(a[3]), "r"(b[0]), "r"(b[1]));
}
__device__ __forceinline__ uint32_t ex2h2(uint32_t x) {
    uint32_t r;
    asm("ex2.approx.f16x2 %0, %1;" : "=r"(r) : "r"(x));
    return r;
}
__device__ __forceinline__ uint32_t packh2(float a, float b) {
    __half2 h = __floats2half2_rn(a, b);
    return *(uint32_t*)&h;
}

// ---------------------------------------------------------------------------
// fp32 -> fp16 planes; grid.y selects (x -> x16) or (y -> y16).
// ---------------------------------------------------------------------------
__global__ __launch_bounds__(256) void conv16x2(const float* __restrict__ x,
                                                const float* __restrict__ y,
                                                __half* __restrict__ dx,
                                                __half* __restrict__ dy) {
    const float* s = blockIdx.y ? y : x;
    __half* d = blockIdx.y ? dy : dx;
    int i = blockIdx.x * 256 + threadIdx.x;
    float4 v = ((const float4*)s)[i];
    __half2 h0 = __floats2half2_rn(v.x, v.y);
    __half2 h1 = __floats2half2_rn(v.z, v.w);
    ((__half2*)d)[2 * i] = h0;
    ((__half2*)d)[2 * i + 1] = h1;
}

// ---------------------------------------------------------------------------
// Transpose weights: z in {0,1,2}: W[1024][1024] -> T[n][1024].
// z==3: Wu[1024][64] -> Wut[64][1024] (only blockIdx.x < 2 active).
// ---------------------------------------------------------------------------
__global__ __launch_bounds__(256) void tsplit16x4(const float* __restrict__ Wk,
                                                  const float* __restrict__ Wv,
                                                  const float* __restrict__ Wq,
                                                  const float* __restrict__ Wu,
                                                  __half* __restrict__ Tk,
                                                  __half* __restrict__ Tv,
                                                  __half* __restrict__ Tq,
                                                  __half* __restrict__ Tu) {
    int z = blockIdx.z;
    if (z == 3 && blockIdx.x >= 2) return;
    const float* W = (z == 0) ? Wk : (z == 1) ? Wv : (z == 2) ? Wq : Wu;
    __half* T = (z == 0) ? Tk : (z == 1) ? Tv : (z == 2) ? Tq : Tu;
    int ncols = (z == 3) ? 64 : EE;
    __shared__ float t[32][33];
    int n0 = blockIdx.x * 32, k0 = blockIdx.y * 32;
    int tx = threadIdx.x & 31, ty = threadIdx.x >> 5;
#pragma unroll
    for (int i = 0; i < 32; i += 8)
        t[ty + i][tx] = W[(size_t)(k0 + ty + i) * ncols + n0 + tx];
    __syncthreads();
#pragma unroll
    for (int i = 0; i < 32; i += 8)
        T[(size_t)(n0 + ty + i) * EE + k0 + tx] = __float2half_rn(t[tx][ty + i]);
}

// ---------------------------------------------------------------------------
// Merged projection GEMMs (z = 0:K, 1:V, 2:Q), 3-stage single-barrier pipeline.
// z==1: output transposed via smem-staged transpose + coalesced STG.
// ---------------------------------------------------------------------------
#define SSTR 72
#define PL16 (128 * SSTR)
#define STG16 (2 * PL16)
#define GSTAGES 3
#define GSM16 (GSTAGES * STG16 * 2)
#define TSTR 136  // transpose staging stride (halves)

__global__ __launch_bounds__(256, 2) void gemm16x3(const __half* __restrict__ X,
                                                   const __half* __restrict__ Y,
                                                   const __half* __restrict__ Wk,
                                                   const __half* __restrict__ Wv,
                                                   const __half* __restrict__ Wq,
                                                   __half* __restrict__ Ck,
                                                   __half* __restrict__ Cv,
                                                   __half* __restrict__ Cq,
                                                   float sk, float sv, float sq) {
    extern __shared__ __half smh[];
    const uint32_t sb0 = smem_u32(smh);
    const int tid = threadIdx.x, lane = tid & 31, wid = tid >> 5;
    const int wm = wid >> 2, wn = wid & 3;
    const int brow = blockIdx.y * 128, bcol = blockIdx.x * 128;
    const int z = blockIdx.z;

    const __half* A = (z == 2) ? Y : X;
    const __half* B = (z == 0) ? Wk : (z == 1) ? Wv : Wq;
    __half* C = (z == 0) ? Ck : (z == 1) ? Cv : Cq;
    const float scale = (z == 0) ? sk : (z == 1) ? sv : sq;

    auto do_stage = [&](int s, int c) {
        uint32_t base = sb0 + s * STG16 * 2;
#pragma unroll
        for (int it = 0; it < 4; it++) {
            int ch = tid + it * 256;
            int row = ch >> 3, kk = (ch & 7) * 8;
            uint32_t so = (uint32_t)(row * SSTR + kk) * 2;
            CPA(base + so, A + (size_t)(brow + row) * EE + c * 64 + kk);
            CPA(base + PL16 * 2 + so, B + (size_t)(bcol + row) * EE + c * 64 + kk);
        }
    };

    float acc[4][4][4];
#pragma unroll
    for (int mi = 0; mi < 4; mi++)
#pragma unroll
        for (int nj = 0; nj < 4; nj++)
#pragma unroll
            for (int q = 0; q < 4; q++) acc[mi][nj][q] = 0.0f;

    const int aro = ((lane >> 3) & 1) * 8 + (lane & 7);
    const int ak = (lane >> 4) * 8;
    const int bro = (lane >> 4) * 8 + (lane & 7);
    const int bk = ((lane >> 3) & 1) * 8;

    do_stage(0, 0);
    CPC();
    do_stage(1, 1);
    CPC();

    int sidx = 0;  // stage holding chunk c0
    for (int c0 = 0; c0 < 16; c0++) {
        if (c0 < 15) { CPW(1); } else { CPW(0); }
        __syncthreads();
        if (c0 + 2 < 16) {
            int ns = sidx + 2;
            if (ns >= GSTAGES) ns -= GSTAGES;
            do_stage(ns, c0 + 2);
            CPC();
        }

        uint32_t uA = sb0 + sidx * STG16 * 2;
        uint32_t uB = uA + PL16 * 2;
#pragma unroll
        for (int ks = 0; ks < 4; ks++) {
            int k0 = ks * 16;
            uint32_t ah[4][4], bh[4][2];
#pragma unroll
            for (int mi = 0; mi < 4; mi++)
                ldsm4(ah[mi], uA + (uint32_t)((wm * 64 + mi * 16 + aro) * SSTR + k0 + ak) * 2);
#pragma unroll
            for (int njp = 0; njp < 2; njp++) {
                uint32_t t4[4];
                ldsm4(t4, uB + (uint32_t)((wn * 32 + njp * 16 + bro) * SSTR + k0 + bk) * 2);
                bh[2 * njp][0] = t4[0]; bh[2 * njp][1] = t4[1];
                bh[2 * njp + 1][0] = t4[2]; bh[2 * njp + 1][1] = t4[3];
            }
#pragma unroll
            for (int mi = 0; mi < 4; mi++)
#pragma unroll
                for (int nj = 0; nj < 4; nj++) mma_f16(acc[mi][nj], ah[mi], bh[nj]);
        }
        sidx = (sidx + 1 == GSTAGES) ? 0 : sidx + 1;
    }

    if (z != 1) {
#pragma unroll
        for (int mi = 0; mi < 4; mi++) {
#pragma unroll
            for (int nj = 0; nj < 4; nj++) {
                int row = brow + wm * 64 + mi * 16 + (lane >> 2);
                int col = bcol + wn * 32 + nj * 8 + (lane & 3) * 2;
                uint32_t p0 = packh2(acc[mi][nj][0] * scale, acc[mi][nj][1] * scale);
                uint32_t p1 = packh2(acc[mi][nj][2] * scale, acc[mi][nj][3] * scale);
                *(uint32_t*)&C[(size_t)row * EE + col] = p0;
                *(uint32_t*)&C[(size_t)(row + 8) * EE + col] = p1;
            }
        }
    } else {
        // transpose via smem (reuse stage 0 after all compute has drained),
        // then fully-coalesced vector stores along the s dimension.
        __syncthreads();
#pragma unroll
        for (int mi = 0; mi < 4; mi++) {
#pragma unroll
            for (int nj = 0; nj < 4; nj++) {
                int row = wm * 64 + mi * 16 + (lane >> 2);
                int col = wn * 32 + nj * 8 + (lane & 3) * 2;
                smh[(col + 0) * TSTR + row] = __float2half_rn(acc[mi][nj][0] * scale);
                smh[(col + 1) * TSTR + row] = __float2half_rn(acc[mi][nj][1] * scale);
                smh[(col + 0) * TSTR + row + 8] = __float2half_rn(acc[mi][nj][2] * scale);
                smh[(col + 1) * TSTR + row + 8] = __float2half_rn(acc[mi][nj][3] * scale);
            }
        }
        __syncthreads();
        int col = tid >> 1, rh = (tid & 1) * 64;
        size_t cbase = (size_t)((brow >> 11) * 1024 + bcol + col) * SS + (brow & 2047) + rh;
#pragma unroll
        for (int i = 0; i < 8; i++)
            *(uint4*)&C[cbase + i * 8] = *(uint4*)&smh[col * TSTR + rh + i * 8];
    }
}

// ---------------------------------------------------------------------------
// Fused attention (128 q-rows, 2 CTAs/SM), single barrier per kv-tile,
// log2-domain softmax, ex2.f16x2 fused with P repack, row-sums via ones-MMA.
// ---------------------------------------------------------------------------
#define ASTR 72
#define QPL (128 * ASTR)
#define KPL (64 * ASTR)
#define FSM ((QPL + 2 * 2 * KPL) * 2)

__global__ __launch_bounds__(256, 2) void flash_mma(const __half* __restrict__ Q,
                                                    const __half* __restrict__ K,
                                                    const __half* __restrict__ V,
                                                    __half* __restrict__ AOh) {
    extern __shared__ __half fsm[];
    const uint32_t sb = smem_u32(fsm);
    const int tid = threadIdx.x, lane = tid & 31, wid = tid >> 5;
    const int qt = blockIdx.x, h = blockIdx.y, b = blockIdx.z;
    const int q2 = (lane & 3) * 2;
    const int rq = wid * 16 + (lane >> 2);

    auto stageKV = [&](int s, int kt) {
        uint32_t base = sb + (QPL + s * 2 * KPL) * 2;
#pragma unroll
        for (int it = 0; it < 2; it++) {
            int ch = tid + it * 256;
            int row = ch >> 3, d8 = (ch & 7) * 8;
            uint32_t so = (uint32_t)(row * ASTR + d8) * 2;
            CPA(base + so, K + (size_t)(b * SS + kt * 64 + row) * EE + h * 64 + d8);
            CPA(base + KPL * 2 + so,
                V + (size_t)(b * 1024 + h * 64 + row) * SS + kt * 64 + d8);
        }
    };

#pragma unroll
    for (int it = 0; it < 4; it++) {
        int ch = tid + it * 256;
        int row = ch >> 3, d8 = (ch & 7) * 8;
        CPA(sb + (uint32_t)(row * ASTR + d8) * 2,
            Q + (size_t)(b * SS + qt * 128 + row) * EE + h * 64 + d8);
    }
    stageKV(0, 0);
    CPC();
    CPW(0);
    __syncthreads();

    const int aro = ((lane >> 3) & 1) * 8 + (lane & 7);
    const int ak = (lane >> 4) * 8;
    const int bro = (lane >> 4) * 8 + (lane & 7);
    const int bk = ((lane >> 3) & 1) * 8;

    uint32_t qf[4][4];
#pragma unroll
    for (int ks = 0; ks < 4; ks++)
        ldsm4(qf[ks], sb + (uint32_t)((wid * 16 + aro) * ASTR + ks * 16 + ak) * 2);

    const uint32_t ones[2] = {0x3C003C00u, 0x3C003C00u};
    float lacc[4] = {0.f, 0.f, 0.f, 0.f};
    float o[8][4];
#pragma unroll
    for (int nt = 0; nt < 8; nt++)
#pragma unroll
        for (int j = 0; j < 4; j++) o[nt][j] = 0.f;

    for (int kt = 0; kt < 32; kt++) {
        if (kt < 31) {
            stageKV((kt + 1) & 1, kt + 1);
            CPC();
        }

        uint32_t uK = sb + (QPL + (kt & 1) * 2 * KPL) * 2;
        uint32_t uV = uK + KPL * 2;

        float s[8][4];
#pragma unroll
        for (int nt = 0; nt < 8; nt++)
#pragma unroll
            for (int j = 0; j < 4; j++) s[nt][j] = 0.f;
#pragma unroll
        for (int ks = 0; ks < 4; ks++) {
            int k0 = ks * 16;
#pragma unroll
            for (int ntp = 0; ntp < 4; ntp++) {
                uint32_t t4[4];
                ldsm4(t4, uK + (uint32_t)((ntp * 16 + bro) * ASTR + k0 + bk) * 2);
                mma_f16(s[2 * ntp], qf[ks], t4);
                mma_f16(s[2 * ntp + 1], qf[ks], t4 + 2);
            }
        }

#pragma unroll
        for (int ks = 0; ks < 4; ks++) {
            int k0 = ks * 16;
            uint32_t a[4];
            a[0] = ex2h2(packh2(s[2 * ks][0], s[2 * ks][1]));
            a[1] = ex2h2(packh2(s[2 * ks][2], s[2 * ks][3]));
            a[2] = ex2h2(packh2(s[2 * ks + 1][0], s[2 * ks + 1][1]));
            a[3] = ex2h2(packh2(s[2 * ks + 1][2], s[2 * ks + 1][3]));
            mma_f16(lacc, a, ones);
#pragma unroll
            for (int ntp = 0; ntp < 4; ntp++) {
                uint32_t t4[4];
                ldsm4(t4, uV + (uint32_t)((ntp * 16 + bro) * ASTR + k0 + bk) * 2);
                mma_f16(o[2 * ntp], a, t4);
                mma_f16(o[2 * ntp + 1], a, t4 + 2);
            }
        }

        if (kt < 31) {
            CPW(0);
            __syncthreads();
        }
    }

    float inv0 = 1.0f / lacc[0], inv1 = 1.0f / lacc[2];
    size_t base = (size_t)(b * SS + qt * 128 + rq) * EE + h * 64;
#pragma unroll
    for (int nt = 0; nt < 8; nt++) {
        uint32_t hi0 = packh2(o[nt][0] * inv0, o[nt][1] * inv0);
        uint32_t hi1 = packh2(o[nt][2] * inv1, o[nt][3] * inv1);
        *(uint32_t*)&AOh[base + nt * 8 + q2] = hi0;
        *(uint32_t*)&AOh[base + (size_t)8 * EE + nt * 8 + q2] = hi1;
    }
}

// ---------------------------------------------------------------------------
// Output projection: C[M,64] = Ao[M,1024] @ Wut^T + bias, single-pass fp16.
// ---------------------------------------------------------------------------
#define PLA (128 * SSTR)
#define PLB (64 * SSTR)
#define OSM ((PLA + PLB) * 2)

__global__ __launch_bounds__(256) void out_mma(const __half* __restrict__ Aoh,
                                               const __half* __restrict__ Wh,
                                               const float* __restrict__ bias,
                                               float* __restrict__ C) {
    extern __shared__ __half osm[];
    const uint32_t sb = smem_u32(osm);
    const int tid = threadIdx.x, lane = tid & 31, wid = tid >> 5;
    const int brow = blockIdx.x * 128;

    const uint32_t uA = sb, uB = sb + PLA * 2;
    const int aro = ((lane >> 3) & 1) * 8 + (lane & 7);
    const int ak = (lane >> 4) * 8;
    const int bro = (lane >> 4) * 8 + (lane & 7);
    const int bk = ((lane >> 3) & 1) * 8;

    float acc[8][4];
#pragma unroll
    for (int nj = 0; nj < 8; nj++)
#pragma unroll
        for (int q = 0; q < 4; q++) acc[nj][q] = 0.0f;

    for (int c0 = 0; c0 < 16; c0++) {
#pragma unroll
        for (int it = 0; it < 4; it++) {
            int ch = tid + it * 256;
            int row = ch >> 3, kk = (ch & 7) * 8;
            *(uint4*)&osm[row * SSTR + kk] =
                *(const uint4*)(Aoh + (size_t)(brow + row) * EE + c0 * 64 + kk);
        }
#pragma unroll
        for (int it = 0; it < 2; it++) {
            int ch = tid + it * 256;
            int row = ch >> 3, kk = (ch & 7) * 8;
            *(uint4*)&osm[PLA + row * SSTR + kk] =
                *(const uint4*)(Wh + (size_t)row * EE + c0 * 64 + kk);
        }
        __syncthreads();

#pragma unroll
        for (int ks = 0; ks < 4; ks++) {
            int k0 = ks * 16;
            uint32_t ah[4], bh[8][2];
            ldsm4(ah, uA + (uint32_t)((wid * 16 + aro) * SSTR + k0 + ak) * 2);
#pragma unroll
            for (int njp = 0; njp < 4; njp++) {
                uint32_t t4[4];
                ldsm4(t4, uB + (uint32_t)((njp * 16 + bro) * SSTR + k0 + bk) * 2);
                bh[2 * njp][0] = t4[0]; bh[2 * njp][1] = t4[1];
                bh[2 * njp + 1][0] = t4[2]; bh[2 * njp + 1][1] = t4[3];
            }
#pragma unroll
            for (int nj = 0; nj < 8; nj++) mma_f16(acc[nj], ah, bh[nj]);
        }
        __syncthreads();
    }

    int row = brow + wid * 16 + (lane >> 2);
    int colb = (lane & 3) * 2;
#pragma unroll
    for (int nj = 0; nj < 8; nj++) {
        int col = nj * 8 + colb;
        float2 bv = *(const float2*)(bias + col);
        float2 w0 = {acc[nj][0] + bv.x, acc[nj][1] + bv.y};
        float2 w1 = {acc[nj][2] + bv.x, acc[nj][3] + bv.y};
        *(float2*)&C[(size_t)row * 64 + col] = w0;
        *(float2*)&C[(size_t)(row + 8) * 64 + col] = w1;
    }
}

// ---------------------------------------------------------------------------
extern "C" void kernel_launch(void* const* d_in, const int* in_sizes, int n_in,
                              void* d_out, int out_size) {
    const float* x = (const float*)d_in[0];
    const float* y = (const float*)d_in[1];
    const float* Wv = (const float*)d_in[2];
    const float* Wk = (const float*)d_in[3];
    const float* Wq = (const float*)d_in[4];
    const float* Wu = (const float*)d_in[5];
    const float* bu = (const float*)d_in[6];
    float* out = (float*)d_out;

    __half *x16, *y16, *wk16, *wv16, *wq16, *qh, *kh, *vth, *aoh, *wuh;
    cudaGetSymbolAddress((void**)&x16, g_x16);
    cudaGetSymbolAddress((void**)&y16, g_y16);
    cudaGetSymbolAddress((void**)&wk16, g_wk16);
    cudaGetSymbolAddress((void**)&wv16, g_wv16);
    cudaGetSymbolAddress((void**)&wq16, g_wq16);
    cudaGetSymbolAddress((void**)&qh, g_qh);
    cudaGetSymbolAddress((void**)&kh, g_kh);
    cudaGetSymbolAddress((void**)&vth, g_vth);
    cudaGetSymbolAddress((void**)&aoh, g_aoh);
    cudaGetSymbolAddress((void**)&wuh, g_wuh);

    const int M = BB * SS;  // 8192
    const float qk_scale = 0.17677669529663687f;           // 1024^-0.25
    const float q_scale = qk_scale * 1.4426950408889634f;  // fold log2(e) into Q

    dim3 gc(M * EE / 1024, 2);
    conv16x2<<<gc, 256>>>(x, y, x16, y16);
    dim3 gt(EE / 32, EE / 32, 4);
    tsplit16x4<<<gt, 256>>>(Wk, Wv, Wq, Wu, wk16, wv16, wq16, wuh);

    cudaFuncSetAttribute(gemm16x3, cudaFuncAttributeMaxDynamicSharedMemorySize, GSM16);
    dim3 gg(EE / 128, M / 128, 3);
    gemm16x3<<<gg, 256, GSM16>>>(x16, y16, wk16, wv16, wq16, kh, vth, qh,
                                 qk_scale, 1.0f, q_scale);

    cudaFuncSetAttribute(flash_mma, cudaFuncAttributeMaxDynamicSharedMemorySize, FSM);
    dim3 ga(SS / 128, HH, BB);
    flash_mma<<<ga, 256, FSM>>>(qh, kh, vth, aoh);

    cudaFuncSetAttribute(out_mma, cudaFuncAttributeMaxDynamicSharedMemorySize, OSM);
    out_mma<<<M / 128, 256, OSM>>>(aoh, wuh, bu, out);
}

// round 17
// speedup vs baseline: 1.0263x; 1.0214x over previous
#include <cuda_runtime.h>
#include <cuda_fp16.h>
#include <cstdint>

#define BB 4
#define SS 2048
#define HH 16
#define EE 1024

// ---------------- static scratch ----------------
__device__ __half g_x16[BB * SS * EE];
__device__ __half g_y16[BB * SS * EE];
__device__ __half g_wk16[EE * EE];
__device__ __half g_wv16[EE * EE];
__device__ __half g_wq16[EE * EE];
__device__ __half g_qh[BB * SS * EE];
__device__ __half g_kh[BB * SS * EE];
__device__ __half g_vth[BB * SS * EE];  // transposed [b*1024 + h*64 + dv][s]
__device__ __half g_aoh[BB * SS * EE];
__device__ __half g_wuh[64 * EE];

// ---------------- helpers ----------------
__device__ __forceinline__ uint32_t smem_u32(const void* p) {
    uint32_t a;
    asm("{ .reg .u64 t; cvta.to.shared.u64 t, %1; cvt.u32.u64 %0, t; }" : "=r"(a) : "l"(p));
    return a;
}
#define CPA(dst, src) asm volatile("cp.async.cg.shared.global [%0], [%1], 16;" ::"r"(dst), "l"(src))
#define CPC() asm volatile("cp.async.commit_group;" ::: "memory")
#define CPW(n) asm volatile("cp.async.wait_group %0;" ::"n"(n) : "memory")

__device__ __forceinline__ void ldsm4(uint32_t* r, uint32_t a) {
    asm volatile("ldmatrix.sync.aligned.m8n8.x4.shared.b16 {%0,%1,%2,%3}, [%4];"
                 : "=r"(r[0]), "=r"(r[1]), "=r"(r[2]), "=r"(r[3]) : "r"(a));
}
__device__ __forceinline__ void mma_f16(float* c, const uint32_t* a, const uint32_t* b) {
    asm volatile(
        "mma.sync.aligned.m16n8k16.row.col.f32.f16.f16.f32 "
        "{%0,%1,%2,%3}, {%4,%5,%6,%7}, {%8,%9}, {%0,%1,%2,%3};"
        : "+f"(c[0]), "+f"(c[1]), "+f"(c[2]), "+f"(c[3])
        : "r"(a[0]), "r"(a[1]), "r"(a[2]), "r"(a[3]), "r"(b[0]), "r"(b[1]));
}
__device__ __forceinline__ uint32_t ex2h2(uint32_t x) {
    uint32_t r;
    asm("ex2.approx.f16x2 %0, %1;" : "=r"(r) : "r"(x));
    return r;
}
__device__ __forceinline__ uint32_t packh2(float a, float b) {
    __half2 h = __floats2half2_rn(a, b);
    return *(uint32_t*)&h;
}

// ---------------------------------------------------------------------------
// Fused preprocessing: one launch.
//   blocks [0, 16384):          fp32->fp16 conversion of x (first half) / y
//   blocks [16384, 16384+3072): transpose Wk/Wv/Wq (1024 blocks each)
//   blocks [19456, 19520):      transpose Wu (64 blocks: 2 x 32)
// ---------------------------------------------------------------------------
#define PREP_BLOCKS (16384 + 3072 + 64)

__global__ __launch_bounds__(256) void prep(const float* __restrict__ x,
                                            const float* __restrict__ y,
                                            const float* __restrict__ Wk,
                                            const float* __restrict__ Wv,
                                            const float* __restrict__ Wq,
                                            const float* __restrict__ Wu,
                                            __half* __restrict__ dx,
                                            __half* __restrict__ dy,
                                            __half* __restrict__ Tk,
                                            __half* __restrict__ Tv,
                                            __half* __restrict__ Tq,
                                            __half* __restrict__ Tu) {
    int blk = blockIdx.x;
    if (blk < 16384) {
        const float* s = (blk < 8192) ? x : y;
        __half* d = (blk < 8192) ? dx : dy;
        int i = (blk & 8191) * 256 + threadIdx.x;
        float4 v = ((const float4*)s)[i];
        __half2 h0 = __floats2half2_rn(v.x, v.y);
        __half2 h1 = __floats2half2_rn(v.z, v.w);
        ((__half2*)d)[2 * i] = h0;
        ((__half2*)d)[2 * i + 1] = h1;
        return;
    }
    int t = blk - 16384;
    const float* W;
    __half* T;
    int n0, k0, ncols;
    if (t < 3072) {
        int z = t >> 10, r = t & 1023;
        W = (z == 0) ? Wk : (z == 1) ? Wv : Wq;
        T = (z == 0) ? Tk : (z == 1) ? Tv : Tq;
        n0 = (r & 31) * 32;
        k0 = (r >> 5) * 32;
        ncols = EE;
    } else {
        int r = t - 3072;
        W = Wu;
        T = Tu;
        n0 = (r & 1) * 32;
        k0 = (r >> 1) * 32;
        ncols = 64;
    }
    __shared__ float tt[32][33];
    int tx = threadIdx.x & 31, ty = threadIdx.x >> 5;
#pragma unroll
    for (int i = 0; i < 32; i += 8)
        tt[ty + i][tx] = W[(size_t)(k0 + ty + i) * ncols + n0 + tx];
    __syncthreads();
#pragma unroll
    for (int i = 0; i < 32; i += 8)
        T[(size_t)(n0 + ty + i) * EE + k0 + tx] = __float2half_rn(tt[tx][ty + i]);
}

// ---------------------------------------------------------------------------
// Merged projection GEMMs (z = 0:K, 1:V, 2:Q), 3-stage single-barrier pipeline.
// z==1: output transposed via smem-staged transpose + coalesced STG.
// ---------------------------------------------------------------------------
#define SSTR 72
#define PL16 (128 * SSTR)
#define STG16 (2 * PL16)
#define GSTAGES 3
#define GSM16 (GSTAGES * STG16 * 2)
#define TSTR 136

__global__ __launch_bounds__(256, 2) void gemm16x3(const __half* __restrict__ X,
                                                   const __half* __restrict__ Y,
                                                   const __half* __restrict__ Wk,
                                                   const __half* __restrict__ Wv,
                                                   const __half* __restrict__ Wq,
                                                   __half* __restrict__ Ck,
                                                   __half* __restrict__ Cv,
                                                   __half* __restrict__ Cq,
                                                   float sk, float sv, float sq) {
    extern __shared__ __half smh[];
    const uint32_t sb0 = smem_u32(smh);
    const int tid = threadIdx.x, lane = tid & 31, wid = tid >> 5;
    const int wm = wid >> 2, wn = wid & 3;
    const int brow = blockIdx.y * 128, bcol = blockIdx.x * 128;
    const int z = blockIdx.z;

    const __half* A = (z == 2) ? Y : X;
    const __half* B = (z == 0) ? Wk : (z == 1) ? Wv : Wq;
    __half* C = (z == 0) ? Ck : (z == 1) ? Cv : Cq;
    const float scale = (z == 0) ? sk : (z == 1) ? sv : sq;

    auto do_stage = [&](int s, int c) {
        uint32_t base = sb0 + s * STG16 * 2;
#pragma unroll
        for (int it = 0; it < 4; it++) {
            int ch = tid + it * 256;
            int row = ch >> 3, kk = (ch & 7) * 8;
            uint32_t so = (uint32_t)(row * SSTR + kk) * 2;
            CPA(base + so, A + (size_t)(brow + row) * EE + c * 64 + kk);
            CPA(base + PL16 * 2 + so, B + (size_t)(bcol + row) * EE + c * 64 + kk);
        }
    };

    float acc[4][4][4];
#pragma unroll
    for (int mi = 0; mi < 4; mi++)
#pragma unroll
        for (int nj = 0; nj < 4; nj++)
#pragma unroll
            for (int q = 0; q < 4; q++) acc[mi][nj][q] = 0.0f;

    const int aro = ((lane >> 3) & 1) * 8 + (lane & 7);
    const int ak = (lane >> 4) * 8;
    const int bro = (lane >> 4) * 8 + (lane & 7);
    const int bk = ((lane >> 3) & 1) * 8;

    do_stage(0, 0);
    CPC();
    do_stage(1, 1);
    CPC();

    int sidx = 0;
    for (int c0 = 0; c0 < 16; c0++) {
        if (c0 < 15) { CPW(1); } else { CPW(0); }
        __syncthreads();
        if (c0 + 2 < 16) {
            int ns = sidx + 2;
            if (ns >= GSTAGES) ns -= GSTAGES;
            do_stage(ns, c0 + 2);
            CPC();
        }

        uint32_t uA = sb0 + sidx * STG16 * 2;
        uint32_t uB = uA + PL16 * 2;
#pragma unroll
        for (int ks = 0; ks < 4; ks++) {
            int k0 = ks * 16;
            uint32_t ah[4][4], bh[4][2];
#pragma unroll
            for (int mi = 0; mi < 4; mi++)
                ldsm4(ah[mi], uA + (uint32_t)((wm * 64 + mi * 16 + aro) * SSTR + k0 + ak) * 2);
#pragma unroll
            for (int njp = 0; njp < 2; njp++) {
                uint32_t t4[4];
                ldsm4(t4, uB + (uint32_t)((wn * 32 + njp * 16 + bro) * SSTR + k0 + bk) * 2);
                bh[2 * njp][0] = t4[0]; bh[2 * njp][1] = t4[1];
                bh[2 * njp + 1][0] = t4[2]; bh[2 * njp + 1][1] = t4[3];
            }
#pragma unroll
            for (int mi = 0; mi < 4; mi++)
#pragma unroll
                for (int nj = 0; nj < 4; nj++) mma_f16(acc[mi][nj], ah[mi], bh[nj]);
        }
        sidx = (sidx + 1 == GSTAGES) ? 0 : sidx + 1;
    }

    if (z != 1) {
#pragma unroll
        for (int mi = 0; mi < 4; mi++) {
#pragma unroll
            for (int nj = 0; nj < 4; nj++) {
                int row = brow + wm * 64 + mi * 16 + (lane >> 2);
                int col = bcol + wn * 32 + nj * 8 + (lane & 3) * 2;
                uint32_t p0 = packh2(acc[mi][nj][0] * scale, acc[mi][nj][1] * scale);
                uint32_t p1 = packh2(acc[mi][nj][2] * scale, acc[mi][nj][3] * scale);
                *(uint32_t*)&C[(size_t)row * EE + col] = p0;
                *(uint32_t*)&C[(size_t)(row + 8) * EE + col] = p1;
            }
        }
    } else {
        __syncthreads();
#pragma unroll
        for (int mi = 0; mi < 4; mi++) {
#pragma unroll
            for (int nj = 0; nj < 4; nj++) {
                int row = wm * 64 + mi * 16 + (lane >> 2);
                int col = wn * 32 + nj * 8 + (lane & 3) * 2;
                smh[(col + 0) * TSTR + row] = __float2half_rn(acc[mi][nj][0] * scale);
                smh[(col + 1) * TSTR + row] = __float2half_rn(acc[mi][nj][1] * scale);
                smh[(col + 0) * TSTR + row + 8] = __float2half_rn(acc[mi][nj][2] * scale);
                smh[(col + 1) * TSTR + row + 8] = __float2half_rn(acc[mi][nj][3] * scale);
            }
        }
        __syncthreads();
        int col = tid >> 1, rh = (tid & 1) * 64;
        size_t cbase = (size_t)((brow >> 11) * 1024 + bcol + col) * SS + (brow & 2047) + rh;
#pragma unroll
        for (int i = 0; i < 8; i++)
            *(uint4*)&C[cbase + i * 8] = *(uint4*)&smh[col * TSTR + rh + i * 8];
    }
}

// ---------------------------------------------------------------------------
// Fused attention (128 q-rows, 2 CTAs/SM), single barrier per kv-tile,
// log2-domain softmax, ex2.f16x2 fused with P repack, row-sums via ones-MMA.
// ---------------------------------------------------------------------------
#define ASTR 72
#define QPL (128 * ASTR)
#define KPL (64 * ASTR)
#define FSM ((QPL + 2 * 2 * KPL) * 2)

__global__ __launch_bounds__(256, 2) void flash_mma(const __half* __restrict__ Q,
                                                    const __half* __restrict__ K,
                                                    const __half* __restrict__ V,
                                                    __half* __restrict__ AOh) {
    extern __shared__ __half fsm[];
    const uint32_t sb = smem_u32(fsm);
    const int tid = threadIdx.x, lane = tid & 31, wid = tid >> 5;
    const int qt = blockIdx.x, h = blockIdx.y, b = blockIdx.z;
    const int q2 = (lane & 3) * 2;
    const int rq = wid * 16 + (lane >> 2);

    auto stageKV = [&](int s, int kt) {
        uint32_t base = sb + (QPL + s * 2 * KPL) * 2;
#pragma unroll
        for (int it = 0; it < 2; it++) {
            int ch = tid + it * 256;
            int row = ch >> 3, d8 = (ch & 7) * 8;
            uint32_t so = (uint32_t)(row * ASTR + d8) * 2;
            CPA(base + so, K + (size_t)(b * SS + kt * 64 + row) * EE + h * 64 + d8);
            CPA(base + KPL * 2 + so,
                V + (size_t)(b * 1024 + h * 64 + row) * SS + kt * 64 + d8);
        }
    };

#pragma unroll
    for (int it = 0; it < 4; it++) {
        int ch = tid + it * 256;
        int row = ch >> 3, d8 = (ch & 7) * 8;
        CPA(sb + (uint32_t)(row * ASTR + d8) * 2,
            Q + (size_t)(b * SS + qt * 128 + row) * EE + h * 64 + d8);
    }
    stageKV(0, 0);
    CPC();
    CPW(0);
    __syncthreads();

    const int aro = ((lane >> 3) & 1) * 8 + (lane & 7);
    const int ak = (lane >> 4) * 8;
    const int bro = (lane >> 4) * 8 + (lane & 7);
    const int bk = ((lane >> 3) & 1) * 8;

    uint32_t qf[4][4];
#pragma unroll
    for (int ks = 0; ks < 4; ks++)
        ldsm4(qf[ks], sb + (uint32_t)((wid * 16 + aro) * ASTR + ks * 16 + ak) * 2);

    const uint32_t ones[2] = {0x3C003C00u, 0x3C003C00u};
    float lacc[4] = {0.f, 0.f, 0.f, 0.f};
    float o[8][4];
#pragma unroll
    for (int nt = 0; nt < 8; nt++)
#pragma unroll
        for (int j = 0; j < 4; j++) o[nt][j] = 0.f;

    for (int kt = 0; kt < 32; kt++) {
        if (kt < 31) {
            stageKV((kt + 1) & 1, kt + 1);
            CPC();
        }

        uint32_t uK = sb + (QPL + (kt & 1) * 2 * KPL) * 2;
        uint32_t uV = uK + KPL * 2;

        float s[8][4];
#pragma unroll
        for (int nt = 0; nt < 8; nt++)
#pragma unroll
            for (int j = 0; j < 4; j++) s[nt][j] = 0.f;
#pragma unroll
        for (int ks = 0; ks < 4; ks++) {
            int k0 = ks * 16;
#pragma unroll
            for (int ntp = 0; ntp < 4; ntp++) {
                uint32_t t4[4];
                ldsm4(t4, uK + (uint32_t)((ntp * 16 + bro) * ASTR + k0 + bk) * 2);
                mma_f16(s[2 * ntp], qf[ks], t4);
                mma_f16(s[2 * ntp + 1], qf[ks], t4 + 2);
            }
        }

#pragma unroll
        for (int ks = 0; ks < 4; ks++) {
            int k0 = ks * 16;
            uint32_t a[4];
            a[0] = ex2h2(packh2(s[2 * ks][0], s[2 * ks][1]));
            a[1] = ex2h2(packh2(s[2 * ks][2], s[2 * ks][3]));
            a[2] = ex2h2(packh2(s[2 * ks + 1][0], s[2 * ks + 1][1]));
            a[3] = ex2h2(packh2(s[2 * ks + 1][2], s[2 * ks + 1][3]));
            mma_f16(lacc, a, ones);
#pragma unroll
            for (int ntp = 0; ntp < 4; ntp++) {
                uint32_t t4[4];
                ldsm4(t4, uV + (uint32_t)((ntp * 16 + bro) * ASTR + k0 + bk) * 2);
                mma_f16(o[2 * ntp], a, t4);
                mma_f16(o[2 * ntp + 1], a, t4 + 2);
            }
        }

        if (kt < 31) {
            CPW(0);
            __syncthreads();
        }
    }

    float inv0 = 1.0f / lacc[0], inv1 = 1.0f / lacc[2];
    size_t base = (size_t)(b * SS + qt * 128 + rq) * EE + h * 64;
#pragma unroll
    for (int nt = 0; nt < 8; nt++) {
        uint32_t hi0 = packh2(o[nt][0] * inv0, o[nt][1] * inv0);
        uint32_t hi1 = packh2(o[nt][2] * inv1, o[nt][3] * inv1);
        *(uint32_t*)&AOh[base + nt * 8 + q2] = hi0;
        *(uint32_t*)&AOh[base + (size_t)8 * EE + nt * 8 + q2] = hi1;
    }
}

// ---------------------------------------------------------------------------
// Output projection, BM=64 for full-chip spread: 128 blocks x 128 threads.
// C[M,64] = Ao[M,1024] @ Wut^T + bias, single-pass fp16.
// ---------------------------------------------------------------------------
#define OPLA (64 * SSTR)
#define OPLB (64 * SSTR)
#define OSM ((OPLA + OPLB) * 2)

__global__ __launch_bounds__(128) void out_mma(const __half* __restrict__ Aoh,
                                               const __half* __restrict__ Wh,
                                               const float* __restrict__ bias,
                                               float* __restrict__ C) {
    extern __shared__ __half osm[];
    const uint32_t sb = smem_u32(osm);
    const int tid = threadIdx.x, lane = tid & 31, wid = tid >> 5;  // 4 warps
    const int brow = blockIdx.x * 64;

    const uint32_t uA = sb, uB = sb + OPLA * 2;
    const int aro = ((lane >> 3) & 1) * 8 + (lane & 7);
    const int ak = (lane >> 4) * 8;
    const int bro = (lane >> 4) * 8 + (lane & 7);
    const int bk = ((lane >> 3) & 1) * 8;

    float acc[8][4];
#pragma unroll
    for (int nj = 0; nj < 8; nj++)
#pragma unroll
        for (int q = 0; q < 4; q++) acc[nj][q] = 0.0f;

    for (int c0 = 0; c0 < 16; c0++) {
#pragma unroll
        for (int it = 0; it < 4; it++) {
            int ch = tid + it * 128;
            int row = ch >> 3, kk = (ch & 7) * 8;
            *(uint4*)&osm[row * SSTR + kk] =
                *(const uint4*)(Aoh + (size_t)(brow + row) * EE + c0 * 64 + kk);
        }
#pragma unroll
        for (int it = 0; it < 4; it++) {
            int ch = tid + it * 128;
            int row = ch >> 3, kk = (ch & 7) * 8;
            *(uint4*)&osm[OPLA + row * SSTR + kk] =
                *(const uint4*)(Wh + (size_t)row * EE + c0 * 64 + kk);
        }
        __syncthreads();

#pragma unroll
        for (int ks = 0; ks < 4; ks++) {
            int k0 = ks * 16;
            uint32_t ah[4], bh[8][2];
            ldsm4(ah, uA + (uint32_t)((wid * 16 + aro) * SSTR + k0 + ak) * 2);
#pragma unroll
            for (int njp = 0; njp < 4; njp++) {
                uint32_t t4[4];
                ldsm4(t4, uB + (uint32_t)((njp * 16 + bro) * SSTR + k0 + bk) * 2);
                bh[2 * njp][0] = t4[0]; bh[2 * njp][1] = t4[1];
                bh[2 * njp + 1][0] = t4[2]; bh[2 * njp + 1][1] = t4[3];
            }
#pragma unroll
            for (int nj = 0; nj < 8; nj++) mma_f16(acc[nj], ah, bh[nj]);
        }
        __syncthreads();
    }

    int row = brow + wid * 16 + (lane >> 2);
    int colb = (lane & 3) * 2;
#pragma unroll
    for (int nj = 0; nj < 8; nj++) {
        int col = nj * 8 + colb;
        float2 bv = *(const float2*)(bias + col);
        float2 w0 = {acc[nj][0] + bv.x, acc[nj][1] + bv.y};
        float2 w1 = {acc[nj][2] + bv.x, acc[nj][3] + bv.y};
        *(float2*)&C[(size_t)row * 64 + col] = w0;
        *(float2*)&C[(size_t)(row + 8) * 64 + col] = w1;
    }
}

// ---------------------------------------------------------------------------
extern "C" void kernel_launch(void* const* d_in, const int* in_sizes, int n_in,
                              void* d_out, int out_size) {
    const float* x = (const float*)d_in[0];
    const float* y = (const float*)d_in[1];
    const float* Wv = (const float*)d_in[2];
    const float* Wk = (const float*)d_in[3];
    const float* Wq = (const float*)d_in[4];
    const float* Wu = (const float*)d_in[5];
    const float* bu = (const float*)d_in[6];
    float* out = (float*)d_out;

    __half *x16, *y16, *wk16, *wv16, *wq16, *qh, *kh, *vth, *aoh, *wuh;
    cudaGetSymbolAddress((void**)&x16, g_x16);
    cudaGetSymbolAddress((void**)&y16, g_y16);
    cudaGetSymbolAddress((void**)&wk16, g_wk16);
    cudaGetSymbolAddress((void**)&wv16, g_wv16);
    cudaGetSymbolAddress((void**)&wq16, g_wq16);
    cudaGetSymbolAddress((void**)&qh, g_qh);
    cudaGetSymbolAddress((void**)&kh, g_kh);
    cudaGetSymbolAddress((void**)&vth, g_vth);
    cudaGetSymbolAddress((void**)&aoh, g_aoh);
    cudaGetSymbolAddress((void**)&wuh, g_wuh);

    const int M = BB * SS;  // 8192
    const float qk_scale = 0.17677669529663687f;           // 1024^-0.25
    const float q_scale = qk_scale * 1.4426950408889634f;  // fold log2(e) into Q

    prep<<<PREP_BLOCKS, 256>>>(x, y, Wk, Wv, Wq, Wu, x16, y16, wk16, wv16, wq16, wuh);

    cudaFuncSetAttribute(gemm16x3, cudaFuncAttributeMaxDynamicSharedMemorySize, GSM16);
    dim3 gg(EE / 128, M / 128, 3);
    gemm16x3<<<gg, 256, GSM16>>>(x16, y16, wk16, wv16, wq16, kh, vth, qh,
                                 qk_scale, 1.0f, q_scale);

    cudaFuncSetAttribute(flash_mma, cudaFuncAttributeMaxDynamicSharedMemorySize, FSM);
    dim3 ga(SS / 128, HH, BB);
    flash_mma<<<ga, 256, FSM>>>(qh, kh, vth, aoh);

    cudaFuncSetAttribute(out_mma, cudaFuncAttributeMaxDynamicSharedMemorySize, OSM);
    out_mma<<<M / 64, 128, OSM>>>(aoh, wuh, bu, out);
}